// round 1
// baseline (speedup 1.0000x reference)
#include <cuda_runtime.h>

#define BB 8
#define CC 64
#define NN 400
#define NN2 (NN * NN)          // 160000
#define KT 32                  // k-tile width in kernel 2/3
#define A_LD (NN + 1)          // 401: coprime with 32 banks -> conflict-free

// Scratch (device globals: no allocation allowed in kernel_launch)
__device__ float g_A[BB * NN2];        // A[b][r][s] = relu(tanh(max_c R[b,c,r,s]))  (5.12 MB)
__device__ float g_x[BB * CC * NN];    // x[b][c][k]                                  (0.82 MB)

// ---------------------------------------------------------------------------
// Kernel 1: channel max + relu(tanh) -> g_A. One float4 per thread, 64 c-planes.
// Coalesced within each c-plane; streaming read of all of R (327 MB).
// ---------------------------------------------------------------------------
__global__ void k1_maxtanh(const float* __restrict__ R) {
    const int per_b = NN2 / 4;                         // 40000 float4 per batch
    int t = blockIdx.x * blockDim.x + threadIdx.x;
    if (t >= BB * per_b) return;
    int b  = t / per_b;
    int i4 = (t - b * per_b) * 4;                      // element offset within plane

    const float4* base =
        reinterpret_cast<const float4*>(R + (size_t)b * CC * NN2 + i4);
    const size_t plane4 = NN2 / 4;                     // float4 stride between c-planes

    // 4 independent max chains for MLP
    float4 m0 = base[0];
    float4 m1 = base[plane4];
    float4 m2 = base[2 * plane4];
    float4 m3 = base[3 * plane4];
    #pragma unroll 4
    for (int c = 4; c < CC; c += 4) {
        float4 v0 = base[(size_t)(c + 0) * plane4];
        float4 v1 = base[(size_t)(c + 1) * plane4];
        float4 v2 = base[(size_t)(c + 2) * plane4];
        float4 v3 = base[(size_t)(c + 3) * plane4];
        m0.x = fmaxf(m0.x, v0.x); m0.y = fmaxf(m0.y, v0.y); m0.z = fmaxf(m0.z, v0.z); m0.w = fmaxf(m0.w, v0.w);
        m1.x = fmaxf(m1.x, v1.x); m1.y = fmaxf(m1.y, v1.y); m1.z = fmaxf(m1.z, v1.z); m1.w = fmaxf(m1.w, v1.w);
        m2.x = fmaxf(m2.x, v2.x); m2.y = fmaxf(m2.y, v2.y); m2.z = fmaxf(m2.z, v2.z); m2.w = fmaxf(m2.w, v2.w);
        m3.x = fmaxf(m3.x, v3.x); m3.y = fmaxf(m3.y, v3.y); m3.z = fmaxf(m3.z, v3.z); m3.w = fmaxf(m3.w, v3.w);
    }
    float4 m;
    m.x = fmaxf(fmaxf(m0.x, m1.x), fmaxf(m2.x, m3.x));
    m.y = fmaxf(fmaxf(m0.y, m1.y), fmaxf(m2.y, m3.y));
    m.z = fmaxf(fmaxf(m0.z, m1.z), fmaxf(m2.z, m3.z));
    m.w = fmaxf(fmaxf(m0.w, m1.w), fmaxf(m2.w, m3.w));

    float4 a;
    a.x = (m.x > 0.f) ? tanhf(m.x) : 0.f;
    a.y = (m.y > 0.f) ? tanhf(m.y) : 0.f;
    a.z = (m.z > 0.f) ? tanhf(m.z) : 0.f;
    a.w = (m.w > 0.f) ? tanhf(m.w) : 0.f;

    reinterpret_cast<float4*>(g_A + (size_t)b * NN2 + i4)[0] = a;
}

// ---------------------------------------------------------------------------
// Kernel 2: x[b,c,k] = sum_n R[b,c,n,k] * A[b,k,n]
// Block: (32 k-lanes, 8 warps). Grid: (13 k-tiles, 4 c-groups, 8 batches).
// Threads across k -> the n-strided reads of R are 128B-coalesced per warp.
// A tile (32 rows x 400) staged in smem, pitch 401 (conflict-free column reads).
// Each thread accumulates 2 channels sharing one smem A read.
// ---------------------------------------------------------------------------
__global__ void k2_gather(const float* __restrict__ R) {
    extern __shared__ float As[];                       // [KT][A_LD]
    const int b  = blockIdx.z;
    const int cg = blockIdx.y;                          // 0..3
    const int k0 = blockIdx.x * KT;
    const int x  = threadIdx.x;                         // 0..31 (k lane)
    const int y  = threadIdx.y;                         // 0..7  (warp)
    const int k  = k0 + x;

    // Stage A rows k0..k0+31 (warp y loads rows y, y+8, y+16, y+24; coalesced)
    for (int r = y; r < KT; r += 8) {
        int row = k0 + r;
        if (row < NN) {
            const float* src = g_A + ((size_t)b * NN + row) * NN;
            for (int n = x; n < NN; n += 32)
                As[r * A_LD + n] = src[n];
        }
    }
    __syncthreads();

    if (k < NN) {
        const int c0 = cg * 16 + y;                     // channel pair: c0, c0+8
        const int c1 = c0 + 8;
        const float* r0p = R + ((size_t)(b * CC + c0) * NN) * NN + k;
        const float* r1p = R + ((size_t)(b * CC + c1) * NN) * NN + k;
        const float* ar  = As + x * A_LD;

        float a0s = 0.f, a1s = 0.f, b0s = 0.f, b1s = 0.f;
        #pragma unroll 4
        for (int n = 0; n < NN; n += 2) {
            float a0 = ar[n];
            float a1 = ar[n + 1];
            a0s += r0p[(size_t)n * NN]       * a0;
            a1s += r0p[(size_t)(n + 1) * NN] * a1;
            b0s += r1p[(size_t)n * NN]       * a0;
            b1s += r1p[(size_t)(n + 1) * NN] * a1;
        }
        g_x[((size_t)b * CC + c0) * NN + k] = a0s + a1s;
        g_x[((size_t)b * CC + c1) * NN + k] = b0s + b1s;
    }
}

// ---------------------------------------------------------------------------
// Kernel 3: out[b,o,k] = sum_c W[o,c] * x[b,c,k] + bias[o]
// Block: (32 k-lanes, 8 warps); each warp handles 8 output channels.
// x tile staged in smem; W rows broadcast via L1. Trivial cost (~0.8 MB traffic).
// ---------------------------------------------------------------------------
__global__ void k3_linear(const float* __restrict__ W,
                          const float* __restrict__ bias,
                          float* __restrict__ out) {
    __shared__ float xs[CC][KT + 1];
    const int b  = blockIdx.z;
    const int k0 = blockIdx.x * KT;
    const int x  = threadIdx.x;
    const int y  = threadIdx.y;
    const int k  = k0 + x;
    const bool valid = (k < NN);

    for (int c = y; c < CC; c += 8)
        xs[c][x] = valid ? g_x[((size_t)b * CC + c) * NN + k] : 0.f;
    __syncthreads();

    for (int o = y; o < CC; o += 8) {
        float acc = bias[o];
        const float* wr = W + o * CC;
        #pragma unroll 16
        for (int c = 0; c < CC; ++c)
            acc += wr[c] * xs[c][x];
        if (valid)
            out[((size_t)b * CC + o) * NN + k] = acc;
    }
}

// ---------------------------------------------------------------------------
extern "C" void kernel_launch(void* const* d_in, const int* in_sizes, int n_in,
                              void* d_out, int out_size) {
    const float* R    = (const float*)d_in[0];
    const float* W    = (const float*)d_in[1];
    const float* bias = (const float*)d_in[2];
    float*       out  = (float*)d_out;

    // Kernel 1: 320000 threads
    {
        int total = BB * (NN2 / 4);
        k1_maxtanh<<<(total + 255) / 256, 256>>>(R);
    }

    // Kernel 2: dynamic smem 32*401*4 = 51328 B (> 48 KB static limit)
    {
        size_t smem = (size_t)KT * A_LD * sizeof(float);
        cudaFuncSetAttribute(k2_gather,
                             cudaFuncAttributeMaxDynamicSharedMemorySize,
                             (int)smem);
        dim3 grid((NN + KT - 1) / KT, 4, BB);   // 13 x 4 x 8 = 416 blocks
        dim3 blk(32, 8);
        k2_gather<<<grid, blk, smem>>>(R);
    }

    // Kernel 3: tiny epilogue
    {
        dim3 grid((NN + KT - 1) / KT, 1, BB);   // 104 blocks
        dim3 blk(32, 8);
        k3_linear<<<grid, blk>>>(W, bias, out);
    }
}